// round 5
// baseline (speedup 1.0000x reference)
#include <cuda_runtime.h>
#include <cuda_bf16.h>
#include <cuda_fp16.h>
#include <cstdint>
#include <cstddef>

// ---------------- static problem sizes -------------------------------------
#define SS      4
#define NH      4
#define CDIM    96
#define HD      24
#define NWIN    4096
#define TOKENS  262144
#define C3      288
#define CH      384

typedef __nv_bfloat16 bf16;

// ---------------- scratch ---------------------------------------------------
__device__ bf16  g_qkv[(size_t)TOKENS * C3];
__device__ bf16  g_o  [(size_t)TOKENS * CDIM];
__device__ float g_x1 [(size_t)TOKENS * CDIM];
__device__ bf16  g_wqkv[C3 * CDIM];
__device__ bf16  g_wproj[CDIM * CDIM];
__device__ bf16  g_wfc1[CH * CDIM];
__device__ bf16  g_wfc2[CDIM * CH];
__device__ float g_bias_exp[16384];

// ---------------- asm helpers ----------------------------------------------
__device__ __forceinline__ void ldm_x4(uint32_t& r0, uint32_t& r1, uint32_t& r2,
                                       uint32_t& r3, uint32_t addr) {
    asm volatile("ldmatrix.sync.aligned.m8n8.x4.shared.b16 {%0,%1,%2,%3}, [%4];\n"
                 : "=r"(r0), "=r"(r1), "=r"(r2), "=r"(r3) : "r"(addr));
}
__device__ __forceinline__ void mma_bf16(float c[4], const uint32_t a[4],
                                         const uint32_t b[2]) {
    asm volatile(
        "mma.sync.aligned.m16n8k16.row.col.f32.bf16.bf16.f32 "
        "{%0,%1,%2,%3},{%4,%5,%6,%7},{%8,%9},{%0,%1,%2,%3};\n"
        : "+f"(c[0]), "+f"(c[1]), "+f"(c[2]), "+f"(c[3])
        : "r"(a[0]), "r"(a[1]), "r"(a[2]), "r"(a[3]), "r"(b[0]), "r"(b[1]));
}
__device__ __forceinline__ void mma_f16(float c[4], const uint32_t a[4],
                                        const uint32_t b[2]) {
    asm volatile(
        "mma.sync.aligned.m16n8k16.row.col.f32.f16.f16.f32 "
        "{%0,%1,%2,%3},{%4,%5,%6,%7},{%8,%9},{%0,%1,%2,%3};\n"
        : "+f"(c[0]), "+f"(c[1]), "+f"(c[2]), "+f"(c[3])
        : "r"(a[0]), "r"(a[1]), "r"(a[2]), "r"(a[3]), "r"(b[0]), "r"(b[1]));
}
__device__ __forceinline__ void cp16(uint32_t dst, const void* src) {
    asm volatile("cp.async.ca.shared.global [%0], [%1], 16;\n"
                 :: "r"(dst), "l"(src));
}
__device__ __forceinline__ void cp_commit() { asm volatile("cp.async.commit_group;\n"); }
__device__ __forceinline__ void cp_wait_all() { asm volatile("cp.async.wait_group 0;\n"); }

__device__ __forceinline__ float exp2_poly(float z) {
    z = fmaxf(z, -100.0f);
    float t = z + 12582912.0f;
    int   n = __float_as_int(t) - 0x4B400000;
    float f = z - (t - 12582912.0f);
    float p = 0.009618129107f;
    p = p * f + 0.05550410866f;
    p = p * f + 0.2402265069f;
    p = p * f + 0.69314718056f;
    p = p * f + 1.0f;
    return p * __int_as_float((n + 127) << 23);
}

// ---------------- weight conversion -----------------------------------------
__global__ void conv_weights(const float* __restrict__ a, const float* __restrict__ b,
                             const float* __restrict__ c, const float* __restrict__ d)
{
    int i = blockIdx.x * 256 + threadIdx.x;
    if (i < C3 * CDIM)   g_wqkv[i]  = __float2bfloat16(a[i]);
    if (i < CDIM * CDIM) g_wproj[i] = __float2bfloat16(b[i]);
    if (i < CH * CDIM) { g_wfc1[i]  = __float2bfloat16(c[i]);
                         g_wfc2[i]  = __float2bfloat16(d[i]); }
}

// ---------------- bias expansion (fragment-ordered, x log2e) ----------------
__global__ void build_bias(const float* __restrict__ rpb)
{
    int idx = blockIdx.x * 256 + threadIdx.x;
    int q    = idx & 3;
    int lane = (idx >> 2) & 31;
    int nt   = (idx >> 7) & 7;
    int mt   = (idx >> 10) & 1;
    int mh   = (idx >> 11) & 1;
    int head = (idx >> 12) & 3;
    int gid = lane >> 2, tig = lane & 3;
    int n = mh*32 + mt*16 + gid + ((q >> 1) << 3);
    int m = nt*8 + tig*2 + (q & 1);
    int ni = n >> 3, nj = n & 7, mi = m >> 3, mj = m & 7;
    int ridx = (ni - mi + 7) * 15 + (nj - mj + 7);
    g_bias_exp[idx] = rpb[ridx * NH + head] * 1.4426950408889634f;
}

// ---------------- fused LN1 + shift/window + QKV GEMM -----------------------
// grid (3, 2048), 256 thr. BM=128, BN=96, K=96 (whole).
__global__ void __launch_bounds__(256)
qkv_fused(const float* __restrict__ x, const float* __restrict__ g1,
          const float* __restrict__ b1, const float* __restrict__ qkvb,
          bf16* __restrict__ out)
{
    __shared__ bf16 As[128][104];
    __shared__ bf16 Bs[96][104];

    const int t = threadIdx.x, warp = t >> 5, lane = t & 31;
    const int bm = blockIdx.y * 128, bn = blockIdx.x * 96;
    const int wrow = warp & 3, wcol = warp >> 2;
    const int gid = lane >> 2, tig = lane & 3;

    // stage weight chunk (96 x 96), full K
    for (int i = t; i < 96 * 12; i += 256) {
        int row = i / 12, c = i % 12;
        cp16((uint32_t)__cvta_generic_to_shared(&Bs[row][c * 8]),
             g_wqkv + (size_t)(bn + row) * CDIM + c * 8);
    }
    cp_commit();

    // LN1 from x with inverse shift/window gather; warp per row
    const float ga = g1[lane*3], gbv = g1[lane*3+1], gc = g1[lane*3+2];
    const float ba = b1[lane*3], bbv = b1[lane*3+1], bc = b1[lane*3+2];
    for (int it = 0; it < 16; it++) {
        int r  = it * 8 + warp;
        int wr = bm + r;
        int w = (wr >> 6) & 63, s = wr & 63;
        int i0 = ((w >> 3) << 3) + (s >> 3), j0 = ((w & 7) << 3) + (s & 7);
        int src = (wr & ~4095) | ((((i0 + SS) & 63) << 6) | ((j0 + SS) & 63));
        const float* xr = x + (size_t)src * CDIM;
        float v0 = xr[lane*3], v1 = xr[lane*3+1], v2 = xr[lane*3+2];
        float sm = v0 + v1 + v2, ssq = v0*v0 + v1*v1 + v2*v2;
        #pragma unroll
        for (int o = 16; o; o >>= 1) {
            sm  += __shfl_xor_sync(0xffffffffu, sm,  o);
            ssq += __shfl_xor_sync(0xffffffffu, ssq, o);
        }
        float mu = sm * (1.0f/CDIM);
        float rs = rsqrtf(ssq * (1.0f/CDIM) - mu*mu + 1e-5f);
        As[r][lane*3+0] = __float2bfloat16((v0 - mu) * rs * ga  + ba);
        As[r][lane*3+1] = __float2bfloat16((v1 - mu) * rs * gbv + bbv);
        As[r][lane*3+2] = __float2bfloat16((v2 - mu) * rs * gc  + bc);
    }
    cp_wait_all();
    __syncthreads();

    float acc[2][6][4];
    #pragma unroll
    for (int i = 0; i < 2; i++)
        #pragma unroll
        for (int j = 0; j < 6; j++)
            #pragma unroll
            for (int q = 0; q < 4; q++) acc[i][j][q] = 0.0f;

    #pragma unroll
    for (int ks = 0; ks < 96; ks += 16) {
        uint32_t af[2][4];
        #pragma unroll
        for (int mt = 0; mt < 2; mt++) {
            int row = wrow * 32 + mt * 16 + (lane & 15);
            int col = ks + ((lane >> 4) << 3);
            uint32_t addr = (uint32_t)__cvta_generic_to_shared(&As[row][col]);
            ldm_x4(af[mt][0], af[mt][1], af[mt][2], af[mt][3], addr);
        }
        uint32_t bfm[6][2];
        #pragma unroll
        for (int pr = 0; pr < 3; pr++) {
            int row = wcol * 48 + pr * 16 + (lane & 7) + ((lane >> 4) << 3);
            int col = ks + (((lane >> 3) & 1) << 3);
            uint32_t addr = (uint32_t)__cvta_generic_to_shared(&Bs[row][col]);
            uint32_t r0, r1, r2, r3;
            ldm_x4(r0, r1, r2, r3, addr);
            bfm[pr*2  ][0] = r0; bfm[pr*2  ][1] = r1;
            bfm[pr*2+1][0] = r2; bfm[pr*2+1][1] = r3;
        }
        #pragma unroll
        for (int mt = 0; mt < 2; mt++)
            #pragma unroll
            for (int nt = 0; nt < 6; nt++)
                mma_bf16(acc[mt][nt], af[mt], bfm[nt]);
    }

    #pragma unroll
    for (int mt = 0; mt < 2; mt++) {
        const int r0 = bm + wrow * 32 + mt * 16 + gid;
        const int r1 = r0 + 8;
        #pragma unroll
        for (int nt = 0; nt < 6; nt++) {
            const int col = bn + wcol * 48 + nt * 8 + tig * 2;
            const float c0 = qkvb[col], c1 = qkvb[col + 1];
            *(__nv_bfloat162*)&out[(size_t)r0 * C3 + col] =
                __nv_bfloat162(__float2bfloat16(acc[mt][nt][0] + c0),
                               __float2bfloat16(acc[mt][nt][1] + c1));
            *(__nv_bfloat162*)&out[(size_t)r1 * C3 + col] =
                __nv_bfloat162(__float2bfloat16(acc[mt][nt][2] + c0),
                               __float2bfloat16(acc[mt][nt][3] + c1));
        }
    }
}

// ---------------- proj GEMM (scatter + x residual), as round 3 --------------
#define SROW 40
__global__ void __launch_bounds__(256)
proj_gemm(const bf16* __restrict__ A, const bf16* __restrict__ W,
          const float* __restrict__ bias, const float* __restrict__ xres,
          float* __restrict__ C)
{
    __shared__ bf16 As[2][128][SROW];
    __shared__ bf16 Bs[2][96][SROW];

    const int t = threadIdx.x;
    const int bm = blockIdx.y * 128;
    const int warp = t >> 5, lane = t & 31;
    const int wrow = warp & 3, wcol = warp >> 2;
    const int gid = lane >> 2, tig = lane & 3;
    const int K = CDIM;

    float acc[2][6][4];
    #pragma unroll
    for (int i = 0; i < 2; i++)
        #pragma unroll
        for (int j = 0; j < 6; j++)
            #pragma unroll
            for (int q = 0; q < 4; q++) acc[i][j][q] = 0.0f;

    auto issue = [&](int kt, int buf) {
        const int k0 = kt << 5;
        #pragma unroll
        for (int c = 0; c < 2; c++) {
            int cid = t + c * 256;
            int row = cid >> 2, cc = cid & 3;
            cp16((uint32_t)__cvta_generic_to_shared(&As[buf][row][cc * 8]),
                 A + (size_t)(bm + row) * K + k0 + cc * 8);
        }
        {
            int row = t >> 2, cc = t & 3;
            cp16((uint32_t)__cvta_generic_to_shared(&Bs[buf][row][cc * 8]),
                 W + (size_t)row * K + k0 + cc * 8);
        }
        if (t < 128) {
            int cid = 256 + t;
            int row = cid >> 2, cc = cid & 3;
            cp16((uint32_t)__cvta_generic_to_shared(&Bs[buf][row][cc * 8]),
                 W + (size_t)row * K + k0 + cc * 8);
        }
        cp_commit();
    };

    issue(0, 0);
    for (int kt = 0; kt < 3; kt++) {
        cp_wait_all();
        __syncthreads();
        if (kt + 1 < 3) issue(kt + 1, (kt + 1) & 1);
        const int buf = kt & 1;
        #pragma unroll
        for (int ks = 0; ks < 32; ks += 16) {
            uint32_t af[2][4];
            #pragma unroll
            for (int mt = 0; mt < 2; mt++) {
                int row = wrow * 32 + mt * 16 + (lane & 15);
                int col = ks + ((lane >> 4) << 3);
                uint32_t addr = (uint32_t)__cvta_generic_to_shared(&As[buf][row][col]);
                ldm_x4(af[mt][0], af[mt][1], af[mt][2], af[mt][3], addr);
            }
            uint32_t bfm[6][2];
            #pragma unroll
            for (int pr = 0; pr < 3; pr++) {
                int row = wcol * 48 + pr * 16 + (lane & 7) + ((lane >> 4) << 3);
                int col = ks + (((lane >> 3) & 1) << 3);
                uint32_t addr = (uint32_t)__cvta_generic_to_shared(&Bs[buf][row][col]);
                uint32_t r0, r1, r2, r3;
                ldm_x4(r0, r1, r2, r3, addr);
                bfm[pr*2  ][0] = r0; bfm[pr*2  ][1] = r1;
                bfm[pr*2+1][0] = r2; bfm[pr*2+1][1] = r3;
            }
            #pragma unroll
            for (int mt = 0; mt < 2; mt++)
                #pragma unroll
                for (int nt = 0; nt < 6; nt++)
                    mma_bf16(acc[mt][nt], af[mt], bfm[nt]);
        }
        __syncthreads();
    }

    #pragma unroll
    for (int mt = 0; mt < 2; mt++) {
        const int r0 = bm + wrow * 32 + mt * 16 + gid;
        const int r1 = r0 + 8;
        int w0 = (r0 >> 6) & 63, s0 = r0 & 63;
        int i0 = ((w0 >> 3) << 3) + (s0 >> 3), j0 = ((w0 & 7) << 3) + (s0 & 7);
        int d0 = (r0 & ~4095) | ((((i0 + SS) & 63) << 6) | ((j0 + SS) & 63));
        int w1 = (r1 >> 6) & 63, s1 = r1 & 63;
        int i1 = ((w1 >> 3) << 3) + (s1 >> 3), j1 = ((w1 & 7) << 3) + (s1 & 7);
        int d1 = (r1 & ~4095) | ((((i1 + SS) & 63) << 6) | ((j1 + SS) & 63));
        #pragma unroll
        for (int nt = 0; nt < 6; nt++) {
            const int col = wcol * 48 + nt * 8 + tig * 2;
            const float c0 = bias[col], c1 = bias[col + 1];
            size_t o0 = (size_t)d0 * CDIM + col;
            size_t o1 = (size_t)d1 * CDIM + col;
            float2 x0 = *(const float2*)&xres[o0];
            float2 x1v = *(const float2*)&xres[o1];
            *(float2*)&C[o0] = make_float2(acc[mt][nt][0] + c0 + x0.x,
                                           acc[mt][nt][1] + c1 + x0.y);
            *(float2*)&C[o1] = make_float2(acc[mt][nt][2] + c0 + x1v.x,
                                           acc[mt][nt][3] + c1 + x1v.y);
        }
    }
}

// ---------------- fused LN2 + FC1 + GELU + FC2 + residual -------------------
// grid 2048, 256 thr, BM=128, dynamic smem 166912 B.
__global__ void __launch_bounds__(256)
mlp_fused(const float* __restrict__ x1, const float* __restrict__ g2,
          const float* __restrict__ b2, const float* __restrict__ fc1b,
          const float* __restrict__ fc2b, float* __restrict__ out)
{
    extern __shared__ char sm_[];
    bf16 (*As)[104] = (bf16(*)[104])sm_;                          // 128 x 104
    bf16 (*Hs)[392] = (bf16(*)[392])(sm_ + 26624);                // 128 x 392
    bf16 (*Ws)[104] = (bf16(*)[104])(sm_ + 26624 + 100352);       // 2 x 96 rows

    const int t = threadIdx.x, warp = t >> 5, lane = t & 31;
    const int bm = blockIdx.x * 128;
    const int wrow = warp & 3, wcol = warp >> 2;
    const int gid = lane >> 2, tig = lane & 3;

    auto issueW1 = [&](int nc, int buf) {
        const bf16* src = g_wfc1 + (size_t)nc * 96 * CDIM;
        for (int i = t; i < 96 * 12; i += 256) {
            int row = i / 12, c = i % 12;
            cp16((uint32_t)__cvta_generic_to_shared(&Ws[buf*96 + row][c * 8]),
                 src + (size_t)row * CDIM + c * 8);
        }
        cp_commit();
    };
    auto issueW2 = [&](int kc, int buf) {
        const bf16* src = g_wfc2 + (size_t)kc * 32;
        for (int i = t; i < 96 * 4; i += 256) {
            int row = i / 4, c = i % 4;
            cp16((uint32_t)__cvta_generic_to_shared(&Ws[buf*96 + row][c * 8]),
                 src + (size_t)row * CH + c * 8);
        }
        cp_commit();
    };

    issueW1(0, 0);

    // LN2 (warp per row)
    {
        const float ga = g2[lane*3], gbv = g2[lane*3+1], gc = g2[lane*3+2];
        const float ba = b2[lane*3], bbv = b2[lane*3+1], bc = b2[lane*3+2];
        for (int it = 0; it < 16; it++) {
            int r = it * 8 + warp;
            const float* xr = x1 + (size_t)(bm + r) * CDIM;
            float v0 = xr[lane*3], v1 = xr[lane*3+1], v2 = xr[lane*3+2];
            float sm = v0 + v1 + v2, ssq = v0*v0 + v1*v1 + v2*v2;
            #pragma unroll
            for (int o = 16; o; o >>= 1) {
                sm  += __shfl_xor_sync(0xffffffffu, sm,  o);
                ssq += __shfl_xor_sync(0xffffffffu, ssq, o);
            }
            float mu = sm * (1.0f/CDIM);
            float rs = rsqrtf(ssq * (1.0f/CDIM) - mu*mu + 1e-5f);
            As[r][lane*3+0] = __float2bfloat16((v0 - mu) * rs * ga  + ba);
            As[r][lane*3+1] = __float2bfloat16((v1 - mu) * rs * gbv + bbv);
            As[r][lane*3+2] = __float2bfloat16((v2 - mu) * rs * gc  + bc);
        }
    }

    // ---- phase 1: H = gelu(A @ W1^T + b1), 4 n-chunks of 96 ----
    for (int nc = 0; nc < 4; nc++) {
        cp_wait_all();
        __syncthreads();
        if (nc < 3) issueW1(nc + 1, (nc + 1) & 1); else issueW2(0, 0);
        const int buf = nc & 1;

        float acc[2][6][4];
        #pragma unroll
        for (int i = 0; i < 2; i++)
            #pragma unroll
            for (int j = 0; j < 6; j++)
                #pragma unroll
                for (int q = 0; q < 4; q++) acc[i][j][q] = 0.0f;

        #pragma unroll
        for (int ks = 0; ks < 96; ks += 16) {
            uint32_t af[2][4];
            #pragma unroll
            for (int mt = 0; mt < 2; mt++) {
                int row = wrow * 32 + mt * 16 + (lane & 15);
                int col = ks + ((lane >> 4) << 3);
                uint32_t addr = (uint32_t)__cvta_generic_to_shared(&As[row][col]);
                ldm_x4(af[mt][0], af[mt][1], af[mt][2], af[mt][3], addr);
            }
            uint32_t bfm[6][2];
            #pragma unroll
            for (int pr = 0; pr < 3; pr++) {
                int row = wcol * 48 + pr * 16 + (lane & 7) + ((lane >> 4) << 3);
                int col = ks + (((lane >> 3) & 1) << 3);
                uint32_t addr = (uint32_t)__cvta_generic_to_shared(&Ws[buf*96 + row][col]);
                uint32_t r0, r1, r2, r3;
                ldm_x4(r0, r1, r2, r3, addr);
                bfm[pr*2  ][0] = r0; bfm[pr*2  ][1] = r1;
                bfm[pr*2+1][0] = r2; bfm[pr*2+1][1] = r3;
            }
            #pragma unroll
            for (int mt = 0; mt < 2; mt++)
                #pragma unroll
                for (int nt = 0; nt < 6; nt++)
                    mma_bf16(acc[mt][nt], af[mt], bfm[nt]);
        }

        // gelu -> Hs
        #pragma unroll
        for (int mt = 0; mt < 2; mt++) {
            const int r0 = wrow * 32 + mt * 16 + gid;
            const int r1 = r0 + 8;
            #pragma unroll
            for (int nt = 0; nt < 6; nt++) {
                const int lcol = wcol * 48 + nt * 8 + tig * 2;
                const int col  = nc * 96 + lcol;
                const float c0 = fc1b[col], c1 = fc1b[col + 1];
                float v00 = acc[mt][nt][0] + c0;
                float v01 = acc[mt][nt][1] + c1;
                float v10 = acc[mt][nt][2] + c0;
                float v11 = acc[mt][nt][3] + c1;
                v00 = 0.5f * v00 * (1.0f + erff(v00 * 0.70710678118654752f));
                v01 = 0.5f * v01 * (1.0f + erff(v01 * 0.70710678118654752f));
                v10 = 0.5f * v10 * (1.0f + erff(v10 * 0.70710678118654752f));
                v11 = 0.5f * v11 * (1.0f + erff(v11 * 0.70710678118654752f));
                *(__nv_bfloat162*)&Hs[r0][col] =
                    __nv_bfloat162(__float2bfloat16(v00), __float2bfloat16(v01));
                *(__nv_bfloat162*)&Hs[r1][col] =
                    __nv_bfloat162(__float2bfloat16(v10), __float2bfloat16(v11));
            }
        }
    }

    // ---- phase 2: out = H @ W2^T + b2 + x1, 12 k-chunks of 32 ----
    float acc[2][6][4];
    #pragma unroll
    for (int i = 0; i < 2; i++)
        #pragma unroll
        for (int j = 0; j < 6; j++)
            #pragma unroll
            for (int q = 0; q < 4; q++) acc[i][j][q] = 0.0f;

    for (int kc = 0; kc < 12; kc++) {
        cp_wait_all();
        __syncthreads();
        if (kc < 11) issueW2(kc + 1, (kc + 1) & 1);
        const int buf = kc & 1;

        #pragma unroll
        for (int ks = 0; ks < 32; ks += 16) {
            uint32_t af[2][4];
            #pragma unroll
            for (int mt = 0; mt < 2; mt++) {
                int row = wrow * 32 + mt * 16 + (lane & 15);
                int col = kc * 32 + ks + ((lane >> 4) << 3);
                uint32_t addr = (uint32_t)__cvta_generic_to_shared(&Hs[row][col]);
                ldm_x4(af[mt][0], af[mt][1], af[mt][2], af[mt][3], addr);
            }
            uint32_t bfm[6][2];
            #pragma unroll
            for (int pr = 0; pr < 3; pr++) {
                int row = wcol * 48 + pr * 16 + (lane & 7) + ((lane >> 4) << 3);
                int col = ks + (((lane >> 3) & 1) << 3);
                uint32_t addr = (uint32_t)__cvta_generic_to_shared(&Ws[buf*96 + row][col]);
                uint32_t r0, r1, r2, r3;
                ldm_x4(r0, r1, r2, r3, addr);
                bfm[pr*2  ][0] = r0; bfm[pr*2  ][1] = r1;
                bfm[pr*2+1][0] = r2; bfm[pr*2+1][1] = r3;
            }
            #pragma unroll
            for (int mt = 0; mt < 2; mt++)
                #pragma unroll
                for (int nt = 0; nt < 6; nt++)
                    mma_bf16(acc[mt][nt], af[mt], bfm[nt]);
        }
    }

    #pragma unroll
    for (int mt = 0; mt < 2; mt++) {
        const int r0 = bm + wrow * 32 + mt * 16 + gid;
        const int r1 = r0 + 8;
        #pragma unroll
        for (int nt = 0; nt < 6; nt++) {
            const int col = wcol * 48 + nt * 8 + tig * 2;
            const float c0 = fc2b[col], c1 = fc2b[col + 1];
            size_t o0 = (size_t)r0 * CDIM + col;
            size_t o1 = (size_t)r1 * CDIM + col;
            float2 x0 = *(const float2*)&x1[o0];
            float2 x1v = *(const float2*)&x1[o1];
            *(float2*)&out[o0] = make_float2(acc[mt][nt][0] + c0 + x0.x,
                                             acc[mt][nt][1] + c1 + x0.y);
            *(float2*)&out[o1] = make_float2(acc[mt][nt][2] + c0 + x1v.x,
                                             acc[mt][nt][3] + c1 + x1v.y);
        }
    }
}

// ---------------- tensor-core windowed attention (unchanged) ----------------
__global__ void __launch_bounds__(256)
attn_tc(const bf16* __restrict__ qkv, bf16* __restrict__ o)
{
    __shared__ __align__(16) __half Vt[NH][32][72];

    const int win  = blockIdx.x;
    const int t    = threadIdx.x;
    const int warp = t >> 5, lane = t & 31;
    const int head = warp >> 1, mh = warp & 1;
    const int gid  = lane >> 2, tig = lane & 3;

    const bf16* wq = qkv + (size_t)win * 64 * C3;

    for (int i = t; i < NH * 64 * HD; i += 256) {
        int h = i / (64 * HD), r = i % (64 * HD);
        int tok = r / HD, d = r % HD;
        Vt[h][d][tok] = __float2half(__bfloat162float(wq[tok * C3 + 192 + h * HD + d]));
    }
    {
        int h = t >> 6, tok = t & 63;
        Vt[h][24][tok] = __float2half(1.0f);
    }
    for (int i = t; i < NH * 7 * 64; i += 256) {
        int h = i / 448, r = i % 448;
        int d = 25 + r / 64, tok = r % 64;
        Vt[h][d][tok] = __float2half(0.0f);
    }
    __syncthreads();

    const bf16* qb = wq + head * HD;
    const bf16* kb = wq + 96 + head * HD;

    uint32_t aq[2][2][4];
    #pragma unroll
    for (int mt = 0; mt < 2; mt++) {
        int r0 = mh * 32 + mt * 16 + gid;
        #pragma unroll
        for (int kt = 0; kt < 2; kt++) {
            int c = kt * 16 + 2 * tig;
            aq[mt][kt][0] = *(const uint32_t*)(qb + (size_t)r0 * C3 + c);
            aq[mt][kt][1] = *(const uint32_t*)(qb + (size_t)(r0 + 8) * C3 + c);
            if (kt == 0) {
                aq[mt][kt][2] = *(const uint32_t*)(qb + (size_t)r0 * C3 + c + 8);
                aq[mt][kt][3] = *(const uint32_t*)(qb + (size_t)(r0 + 8) * C3 + c + 8);
            } else { aq[mt][kt][2] = 0u; aq[mt][kt][3] = 0u; }
        }
    }
    uint32_t bk[8][2][2];
    #pragma unroll
    for (int nt = 0; nt < 8; nt++) {
        int tok = nt * 8 + gid;
        #pragma unroll
        for (int kt = 0; kt < 2; kt++) {
            int c = kt * 16 + 2 * tig;
            bk[nt][kt][0] = *(const uint32_t*)(kb + (size_t)tok * C3 + c);
            bk[nt][kt][1] = (kt == 0) ? *(const uint32_t*)(kb + (size_t)tok * C3 + c + 8) : 0u;
        }
    }

    float acc[2][8][4];
    #pragma unroll
    for (int mt = 0; mt < 2; mt++)
        #pragma unroll
        for (int nt = 0; nt < 8; nt++)
            #pragma unroll
            for (int q = 0; q < 4; q++) acc[mt][nt][q] = 0.0f;

    #pragma unroll
    for (int mt = 0; mt < 2; mt++)
        #pragma unroll
        for (int nt = 0; nt < 8; nt++)
            #pragma unroll
            for (int kt = 0; kt < 2; kt++)
                mma_bf16(acc[mt][nt], aq[mt][kt], bk[nt][kt]);

    const int wimg = win & 63;
    const int wi = wimg >> 3, wj = wimg & 7;
    int rk[8];
    #pragma unroll
    for (int nt = 0; nt < 8; nt++) {
        int mrow = nt;
        int mcol = 2 * tig;
        rk[nt] = ((wi == 7) ? ((mrow < 4) ? 1 : 2) : 0) * 3
               + ((wj == 7) ? ((mcol < 4) ? 1 : 2) : 0);
    }

    const float K1 = 0.2944888985f;
    const float MASKL2 = -144.269504089f;

    uint32_t p01[2][8], p23[2][8];
    #pragma unroll
    for (int mt = 0; mt < 2; mt++) {
        int n0 = mh * 32 + mt * 16 + gid;
        int n1 = n0 + 8;
        int rq0 = ((wi == 7) ? (((n0 >> 3) < 4) ? 1 : 2) : 0) * 3
                + ((wj == 7) ? (((n0 & 7) < 4) ? 1 : 2) : 0);
        int rq1 = ((wi == 7) ? (((n1 >> 3) < 4) ? 1 : 2) : 0) * 3
                + ((wj == 7) ? (((n1 & 7) < 4) ? 1 : 2) : 0);
        #pragma unroll
        for (int nt = 0; nt < 8; nt++) {
            const float4 bb = *(const float4*)&g_bias_exp[
                (((((head * 2 + mh) * 2 + mt) * 8 + nt) * 32 + lane) << 2)];
            float m0 = (rq0 != rk[nt]) ? MASKL2 : 0.0f;
            float m1 = (rq1 != rk[nt]) ? MASKL2 : 0.0f;
            float e00 = exp2_poly(acc[mt][nt][0] * K1 + bb.x + m0);
            float e01 = exp2_poly(acc[mt][nt][1] * K1 + bb.y + m0);
            float e10 = exp2_poly(acc[mt][nt][2] * K1 + bb.z + m1);
            float e11 = exp2_poly(acc[mt][nt][3] * K1 + bb.w + m1);
            __half2 h01 = __floats2half2_rn(e00, e01);
            __half2 h23 = __floats2half2_rn(e10, e11);
            p01[mt][nt] = *(uint32_t*)&h01;
            p23[mt][nt] = *(uint32_t*)&h23;
        }
    }

    uint32_t bv[4][4][2];
    #pragma unroll
    for (int np = 0; np < 2; np++) {
        #pragma unroll
        for (int kt = 0; kt < 4; kt++) {
            int row = np * 16 + (lane & 7) + ((lane >> 4) << 3);
            int col = kt * 16 + (((lane >> 3) & 1) << 3);
            uint32_t addr = (uint32_t)__cvta_generic_to_shared(&Vt[head][row][col]);
            uint32_t r0, r1, r2, r3;
            ldm_x4(r0, r1, r2, r3, addr);
            bv[np*2  ][kt][0] = r0; bv[np*2  ][kt][1] = r1;
            bv[np*2+1][kt][0] = r2; bv[np*2+1][kt][1] = r3;
        }
    }

    float ao[2][4][4];
    #pragma unroll
    for (int mt = 0; mt < 2; mt++)
        #pragma unroll
        for (int nv = 0; nv < 4; nv++)
            #pragma unroll
            for (int q = 0; q < 4; q++) ao[mt][nv][q] = 0.0f;

    #pragma unroll
    for (int mt = 0; mt < 2; mt++) {
        #pragma unroll
        for (int kt = 0; kt < 4; kt++) {
            uint32_t ap[4] = { p01[mt][2*kt], p23[mt][2*kt],
                               p01[mt][2*kt+1], p23[mt][2*kt+1] };
            #pragma unroll
            for (int nv = 0; nv < 4; nv++)
                mma_f16(ao[mt][nv], ap, bv[nv][kt]);
        }
    }

    #pragma unroll
    for (int mt = 0; mt < 2; mt++) {
        float sum0 = __shfl_sync(0xffffffffu, ao[mt][3][0], lane & 28);
        float sum1 = __shfl_sync(0xffffffffu, ao[mt][3][2], lane & 28);
        float inv0 = __fdividef(1.0f, sum0);
        float inv1 = __fdividef(1.0f, sum1);
        int row0 = win * 64 + mh * 32 + mt * 16 + gid;
        #pragma unroll
        for (int nv = 0; nv < 3; nv++) {
            int col = head * HD + nv * 8 + tig * 2;
            *(__nv_bfloat162*)&o[(size_t)row0 * CDIM + col] =
                __nv_bfloat162(__float2bfloat16(ao[mt][nv][0] * inv0),
                               __float2bfloat16(ao[mt][nv][1] * inv0));
            *(__nv_bfloat162*)&o[(size_t)(row0 + 8) * CDIM + col] =
                __nv_bfloat162(__float2bfloat16(ao[mt][nv][2] * inv1),
                               __float2bfloat16(ao[mt][nv][3] * inv1));
        }
    }
}

// ---------------- launch ----------------------------------------------------
extern "C" void kernel_launch(void* const* d_in, const int* in_sizes, int n_in,
                              void* d_out, int out_size)
{
    const float* x       = (const float*)d_in[0];
    const float* norm1_g = (const float*)d_in[1];
    const float* norm1_b = (const float*)d_in[2];
    const float* qkv_w   = (const float*)d_in[3];
    const float* qkv_b   = (const float*)d_in[4];
    const float* rpb     = (const float*)d_in[5];
    const float* proj_w  = (const float*)d_in[6];
    const float* proj_b  = (const float*)d_in[7];
    const float* norm2_g = (const float*)d_in[8];
    const float* norm2_b = (const float*)d_in[9];
    const float* fc1_w   = (const float*)d_in[10];
    const float* fc1_b   = (const float*)d_in[11];
    const float* fc2_w   = (const float*)d_in[12];
    const float* fc2_b   = (const float*)d_in[13];
    float* out = (float*)d_out;

    bf16 *qkv_p, *o_p;
    bf16 *wproj_p;
    float *x1_p;
    cudaGetSymbolAddress((void**)&qkv_p,  g_qkv);
    cudaGetSymbolAddress((void**)&o_p,    g_o);
    cudaGetSymbolAddress((void**)&x1_p,   g_x1);
    cudaGetSymbolAddress((void**)&wproj_p,g_wproj);

    static int smem_set = 0;
    if (!smem_set) {
        cudaFuncSetAttribute(mlp_fused, cudaFuncAttributeMaxDynamicSharedMemorySize,
                             166912);
        smem_set = 1;
    }

    conv_weights<<<(CH*CDIM + 255)/256, 256>>>(qkv_w, proj_w, fc1_w, fc2_w);
    build_bias<<<64, 256>>>(rpb);

    // LN1 + shift/window + QKV
    qkv_fused<<<dim3(3, TOKENS/128), 256>>>(x, norm1_g, norm1_b, qkv_b, qkv_p);

    // attention
    attn_tc<<<NWIN, 256>>>(qkv_p, o_p);

    // proj + window-reverse + residual
    proj_gemm<<<dim3(1, TOKENS/128), 256>>>(o_p, wproj_p, proj_b, x, x1_p);

    // LN2 + FC1 + GELU + FC2 + residual
    mlp_fused<<<TOKENS/128, 256, 166912>>>(x1_p, norm2_g, norm2_b,
                                           fc1_b, fc2_b, out);
}

// round 6
// speedup vs baseline: 1.2005x; 1.2005x over previous
#include <cuda_runtime.h>
#include <cuda_bf16.h>
#include <cuda_fp16.h>
#include <cstdint>
#include <cstddef>

// ---------------- static problem sizes -------------------------------------
#define SS      4
#define NH      4
#define CDIM    96
#define HD      24
#define NWIN    4096
#define TOKENS  262144
#define C3      288
#define CH      384

typedef __nv_bfloat16 bf16;

// ---------------- scratch ---------------------------------------------------
__device__ bf16  g_hw [(size_t)TOKENS * CDIM];
__device__ bf16  g_qkv[(size_t)TOKENS * C3];
__device__ bf16  g_o  [(size_t)TOKENS * CDIM];
__device__ float g_x1 [(size_t)TOKENS * CDIM];
__device__ bf16  g_h2 [(size_t)TOKENS * CDIM];
__device__ bf16  g_fc1[(size_t)TOKENS * CH];
__device__ bf16  g_wqkv[C3 * CDIM];
__device__ bf16  g_wproj[CDIM * CDIM];
__device__ bf16  g_wfc1[CH * CDIM];
__device__ bf16  g_wfc2[CDIM * CH];
__device__ float g_bias_exp[16384];

// ---------------- asm helpers ----------------------------------------------
__device__ __forceinline__ void ldm_x4(uint32_t& r0, uint32_t& r1, uint32_t& r2,
                                       uint32_t& r3, uint32_t addr) {
    asm volatile("ldmatrix.sync.aligned.m8n8.x4.shared.b16 {%0,%1,%2,%3}, [%4];\n"
                 : "=r"(r0), "=r"(r1), "=r"(r2), "=r"(r3) : "r"(addr));
}
__device__ __forceinline__ void mma_bf16(float c[4], const uint32_t a[4],
                                         const uint32_t b[2]) {
    asm volatile(
        "mma.sync.aligned.m16n8k16.row.col.f32.bf16.bf16.f32 "
        "{%0,%1,%2,%3},{%4,%5,%6,%7},{%8,%9},{%0,%1,%2,%3};\n"
        : "+f"(c[0]), "+f"(c[1]), "+f"(c[2]), "+f"(c[3])
        : "r"(a[0]), "r"(a[1]), "r"(a[2]), "r"(a[3]), "r"(b[0]), "r"(b[1]));
}
__device__ __forceinline__ void mma_f16(float c[4], const uint32_t a[4],
                                        const uint32_t b[2]) {
    asm volatile(
        "mma.sync.aligned.m16n8k16.row.col.f32.f16.f16.f32 "
        "{%0,%1,%2,%3},{%4,%5,%6,%7},{%8,%9},{%0,%1,%2,%3};\n"
        : "+f"(c[0]), "+f"(c[1]), "+f"(c[2]), "+f"(c[3])
        : "r"(a[0]), "r"(a[1]), "r"(a[2]), "r"(a[3]), "r"(b[0]), "r"(b[1]));
}
__device__ __forceinline__ void cp16(uint32_t dst, const void* src) {
    asm volatile("cp.async.ca.shared.global [%0], [%1], 16;\n"
                 :: "r"(dst), "l"(src));
}
__device__ __forceinline__ void cp_commit() { asm volatile("cp.async.commit_group;\n"); }
__device__ __forceinline__ void cp_wait_all() { asm volatile("cp.async.wait_group 0;\n"); }

__device__ __forceinline__ float exp2_poly(float z) {
    z = fmaxf(z, -100.0f);
    float t = z + 12582912.0f;
    int   n = __float_as_int(t) - 0x4B400000;
    float f = z - (t - 12582912.0f);
    float p = 0.009618129107f;
    p = p * f + 0.05550410866f;
    p = p * f + 0.2402265069f;
    p = p * f + 0.69314718056f;
    p = p * f + 1.0f;
    return p * __int_as_float((n + 127) << 23);
}

// ---------------- weight conversion -----------------------------------------
__global__ void conv_weights(const float* __restrict__ a, const float* __restrict__ b,
                             const float* __restrict__ c, const float* __restrict__ d)
{
    int i = blockIdx.x * 256 + threadIdx.x;
    if (i < C3 * CDIM)   g_wqkv[i]  = __float2bfloat16(a[i]);
    if (i < CDIM * CDIM) g_wproj[i] = __float2bfloat16(b[i]);
    if (i < CH * CDIM) { g_wfc1[i]  = __float2bfloat16(c[i]);
                         g_wfc2[i]  = __float2bfloat16(d[i]); }
}

// ---------------- bias expansion (fragment-ordered, x log2e) ----------------
__global__ void build_bias(const float* __restrict__ rpb)
{
    int idx = blockIdx.x * 256 + threadIdx.x;
    int q    = idx & 3;
    int lane = (idx >> 2) & 31;
    int nt   = (idx >> 7) & 7;
    int mt   = (idx >> 10) & 1;
    int mh   = (idx >> 11) & 1;
    int head = (idx >> 12) & 3;
    int gid = lane >> 2, tig = lane & 3;
    int n = mh*32 + mt*16 + gid + ((q >> 1) << 3);
    int m = nt*8 + tig*2 + (q & 1);
    int ni = n >> 3, nj = n & 7, mi = m >> 3, mj = m & 7;
    int ridx = (ni - mi + 7) * 15 + (nj - mj + 7);
    g_bias_exp[idx] = rpb[ridx * NH + head] * 1.4426950408889634f;
}

// ---------------- LN1 + shift + window partition (bf16 out) ----------------
__global__ void ln1_shift_window(const float* __restrict__ x,
                                 const float* __restrict__ g,
                                 const float* __restrict__ b,
                                 bf16* __restrict__ out)
{
    int tok  = blockIdx.x * 4 + (threadIdx.x >> 5);
    int lane = threadIdx.x & 31;
    const float* xr = x + (size_t)tok * CDIM;
    float v0 = xr[lane*3+0], v1 = xr[lane*3+1], v2 = xr[lane*3+2];
    float s  = v0 + v1 + v2;
    float ss = v0*v0 + v1*v1 + v2*v2;
    #pragma unroll
    for (int o = 16; o; o >>= 1) {
        s  += __shfl_xor_sync(0xffffffffu, s,  o);
        ss += __shfl_xor_sync(0xffffffffu, ss, o);
    }
    float mu  = s * (1.0f/CDIM);
    float var = ss * (1.0f/CDIM) - mu*mu;
    float r   = rsqrtf(var + 1e-5f);

    int bimg = tok >> 12;
    int hw   = tok & 4095;
    int hi   = hw >> 6, wj = hw & 63;
    int i = (hi + 60) & 63;
    int j = (wj + 60) & 63;
    int dtok = ((bimg * 64 + (i >> 3) * 8 + (j >> 3)) << 6) + ((i & 7) << 3) + (j & 7);
    bf16* orow = out + (size_t)dtok * CDIM;
    orow[lane*3+0] = __float2bfloat16((v0 - mu) * r * g[lane*3+0] + b[lane*3+0]);
    orow[lane*3+1] = __float2bfloat16((v1 - mu) * r * g[lane*3+1] + b[lane*3+1]);
    orow[lane*3+2] = __float2bfloat16((v2 - mu) * r * g[lane*3+2] + b[lane*3+2]);
}

// ---------------- plain LN (bf16 out) ---------------------------------------
__global__ void ln_plain(const float* __restrict__ x,
                         const float* __restrict__ g,
                         const float* __restrict__ b,
                         bf16* __restrict__ out)
{
    int tok  = blockIdx.x * 4 + (threadIdx.x >> 5);
    int lane = threadIdx.x & 31;
    const float* xr = x + (size_t)tok * CDIM;
    float v0 = xr[lane*3+0], v1 = xr[lane*3+1], v2 = xr[lane*3+2];
    float s  = v0 + v1 + v2;
    float ss = v0*v0 + v1*v1 + v2*v2;
    #pragma unroll
    for (int o = 16; o; o >>= 1) {
        s  += __shfl_xor_sync(0xffffffffu, s,  o);
        ss += __shfl_xor_sync(0xffffffffu, ss, o);
    }
    float mu  = s * (1.0f/CDIM);
    float var = ss * (1.0f/CDIM) - mu*mu;
    float r   = rsqrtf(var + 1e-5f);
    bf16* orow = out + (size_t)tok * CDIM;
    orow[lane*3+0] = __float2bfloat16((v0 - mu) * r * g[lane*3+0] + b[lane*3+0]);
    orow[lane*3+1] = __float2bfloat16((v1 - mu) * r * g[lane*3+1] + b[lane*3+1]);
    orow[lane*3+2] = __float2bfloat16((v2 - mu) * r * g[lane*3+2] + b[lane*3+2]);
}

// ---------------- bf16 tensor-core GEMM (R4 version) -------------------------
#define SROW 40

template<int MODE>
__global__ void __launch_bounds__(256)
gemm_bf16(const bf16* __restrict__ A, const bf16* __restrict__ W,
          const float* __restrict__ bias, const float* __restrict__ aux,
          void* __restrict__ Cout, int K, int N)
{
    __shared__ bf16 As[2][128][SROW];
    __shared__ bf16 Bs[2][96][SROW];

    const int t    = threadIdx.x;
    const int bm   = blockIdx.y * 128;
    const int bn   = blockIdx.x * 96;
    const int warp = t >> 5, lane = t & 31;
    const int wrow = warp & 3;
    const int wcol = warp >> 2;
    const int gid  = lane >> 2, tig = lane & 3;

    float acc[2][6][4];
    #pragma unroll
    for (int i = 0; i < 2; i++)
        #pragma unroll
        for (int j = 0; j < 6; j++)
            #pragma unroll
            for (int q = 0; q < 4; q++) acc[i][j][q] = 0.0f;

    const int nk = K >> 5;

    auto issue = [&](int kt, int buf) {
        const int k0 = kt << 5;
        #pragma unroll
        for (int c = 0; c < 2; c++) {
            int cid = t + c * 256;
            int row = cid >> 2, cc = cid & 3;
            cp16((uint32_t)__cvta_generic_to_shared(&As[buf][row][cc * 8]),
                 A + (size_t)(bm + row) * K + k0 + cc * 8);
        }
        {
            int row = t >> 2, cc = t & 3;
            cp16((uint32_t)__cvta_generic_to_shared(&Bs[buf][row][cc * 8]),
                 W + (size_t)(bn + row) * K + k0 + cc * 8);
        }
        if (t < 128) {
            int cid = 256 + t;
            int row = cid >> 2, cc = cid & 3;
            cp16((uint32_t)__cvta_generic_to_shared(&Bs[buf][row][cc * 8]),
                 W + (size_t)(bn + row) * K + k0 + cc * 8);
        }
        cp_commit();
    };

    issue(0, 0);

    for (int kt = 0; kt < nk; kt++) {
        cp_wait_all();
        __syncthreads();
        if (kt + 1 < nk) issue(kt + 1, (kt + 1) & 1);
        const int buf = kt & 1;

        #pragma unroll
        for (int ks = 0; ks < 32; ks += 16) {
            uint32_t af[2][4];
            #pragma unroll
            for (int mt = 0; mt < 2; mt++) {
                int row = wrow * 32 + mt * 16 + (lane & 15);
                int col = ks + ((lane >> 4) << 3);
                uint32_t addr = (uint32_t)__cvta_generic_to_shared(&As[buf][row][col]);
                ldm_x4(af[mt][0], af[mt][1], af[mt][2], af[mt][3], addr);
            }
            uint32_t bfm[6][2];
            #pragma unroll
            for (int pr = 0; pr < 3; pr++) {
                int row = wcol * 48 + pr * 16 + (lane & 7) + ((lane >> 4) << 3);
                int col = ks + (((lane >> 3) & 1) << 3);
                uint32_t addr = (uint32_t)__cvta_generic_to_shared(&Bs[buf][row][col]);
                uint32_t r0, r1, r2, r3;
                ldm_x4(r0, r1, r2, r3, addr);
                bfm[pr*2  ][0] = r0; bfm[pr*2  ][1] = r1;
                bfm[pr*2+1][0] = r2; bfm[pr*2+1][1] = r3;
            }
            #pragma unroll
            for (int mt = 0; mt < 2; mt++)
                #pragma unroll
                for (int nt = 0; nt < 6; nt++)
                    mma_bf16(acc[mt][nt], af[mt], bfm[nt]);
        }
        __syncthreads();
    }

    #pragma unroll
    for (int mt = 0; mt < 2; mt++) {
        const int r0 = bm + wrow * 32 + mt * 16 + gid;
        const int r1 = r0 + 8;
        int d0 = r0, d1 = r1;
        if (MODE == 1) {
            int w0 = (r0 >> 6) & 63, s0 = r0 & 63;
            int i0 = ((w0 >> 3) << 3) + (s0 >> 3), j0 = ((w0 & 7) << 3) + (s0 & 7);
            d0 = (r0 & ~4095) | ((((i0 + SS) & 63) << 6) | ((j0 + SS) & 63));
            int w1 = (r1 >> 6) & 63, s1 = r1 & 63;
            int i1 = ((w1 >> 3) << 3) + (s1 >> 3), j1 = ((w1 & 7) << 3) + (s1 & 7);
            d1 = (r1 & ~4095) | ((((i1 + SS) & 63) << 6) | ((j1 + SS) & 63));
        }
        #pragma unroll
        for (int nt = 0; nt < 6; nt++) {
            const int col = bn + wcol * 48 + nt * 8 + tig * 2;
            const float b0 = bias[col], b1 = bias[col + 1];
            float v00 = acc[mt][nt][0] + b0;
            float v01 = acc[mt][nt][1] + b1;
            float v10 = acc[mt][nt][2] + b0;
            float v11 = acc[mt][nt][3] + b1;
            if (MODE == 0) {
                bf16* C = (bf16*)Cout;
                *(__nv_bfloat162*)&C[(size_t)r0 * N + col] =
                    __nv_bfloat162(__float2bfloat16(v00), __float2bfloat16(v01));
                *(__nv_bfloat162*)&C[(size_t)r1 * N + col] =
                    __nv_bfloat162(__float2bfloat16(v10), __float2bfloat16(v11));
            } else if (MODE == 1) {
                float* C = (float*)Cout;
                size_t o0 = (size_t)d0 * CDIM + col;
                size_t o1 = (size_t)d1 * CDIM + col;
                float2 x0 = *(const float2*)&aux[o0];
                float2 x1v = *(const float2*)&aux[o1];
                *(float2*)&C[o0] = make_float2(v00 + x0.x,  v01 + x0.y);
                *(float2*)&C[o1] = make_float2(v10 + x1v.x, v11 + x1v.y);
            } else if (MODE == 2) {
                v00 = 0.5f * v00 * (1.0f + erff(v00 * 0.70710678118654752f));
                v01 = 0.5f * v01 * (1.0f + erff(v01 * 0.70710678118654752f));
                v10 = 0.5f * v10 * (1.0f + erff(v10 * 0.70710678118654752f));
                v11 = 0.5f * v11 * (1.0f + erff(v11 * 0.70710678118654752f));
                bf16* C = (bf16*)Cout;
                *(__nv_bfloat162*)&C[(size_t)r0 * N + col] =
                    __nv_bfloat162(__float2bfloat16(v00), __float2bfloat16(v01));
                *(__nv_bfloat162*)&C[(size_t)r1 * N + col] =
                    __nv_bfloat162(__float2bfloat16(v10), __float2bfloat16(v11));
            } else {
                float* C = (float*)Cout;
                float2 x0 = *(const float2*)&aux[(size_t)r0 * N + col];
                float2 x1v = *(const float2*)&aux[(size_t)r1 * N + col];
                *(float2*)&C[(size_t)r0 * N + col] = make_float2(v00 + x0.x,  v01 + x0.y);
                *(float2*)&C[(size_t)r1 * N + col] = make_float2(v10 + x1v.x, v11 + x1v.y);
            }
        }
    }
}

// ---------------- tensor-core windowed attention (smem-staged) --------------
// dynamic smem: S[64][296] bf16 (37888 B) + Vt[4][32][72] half (18432 B)
#define ATTN_SMEM (37888 + 18432)

__global__ void __launch_bounds__(256)
attn_tc(const bf16* __restrict__ qkv, bf16* __restrict__ o)
{
    extern __shared__ __align__(16) char sm_[];
    bf16  (*S)[296]      = (bf16(*)[296])sm_;
    __half (*Vt)[32][72] = (__half(*)[32][72])(sm_ + 37888);

    const int win  = blockIdx.x;
    const int t    = threadIdx.x;
    const int warp = t >> 5, lane = t & 31;
    const int head = warp >> 1, mh = warp & 1;
    const int gid  = lane >> 2, tig = lane & 3;

    const bf16* wq = qkv + (size_t)win * 64 * C3;

    // ---- stage QKV window tile: 64 x 288, coalesced 16B chunks ----
    #pragma unroll
    for (int i = 0; i < 9; i++) {
        int cid = t + i * 256;            // 0..2303
        int row = cid / 36, c = cid % 36;
        cp16((uint32_t)__cvta_generic_to_shared(&S[row][c * 8]),
             wq + (size_t)row * C3 + c * 8);
    }
    cp_commit();
    cp_wait_all();
    __syncthreads();

    // ---- build V^T (f16) with ones row (d=24) and zero pad ----
    {
        int tok = t & 63, h = t >> 6;
        const bf16* vsrc = &S[tok][192 + h * HD];
        #pragma unroll
        for (int d = 0; d < HD; d++)
            Vt[h][d][tok] = __float2half(__bfloat162float(vsrc[d]));
        Vt[h][24][tok] = __float2half(1.0f);
        #pragma unroll
        for (int d = 25; d < 32; d++)
            Vt[h][d][tok] = __float2half(0.0f);
    }

    // ---- load Q (A-frags) and K (B-frags) from smem ----
    const int qc = head * HD;
    const int kc = 96 + head * HD;

    uint32_t aq[2][2][4];
    #pragma unroll
    for (int mt = 0; mt < 2; mt++) {
        int r0 = mh * 32 + mt * 16 + gid;
        #pragma unroll
        for (int kt = 0; kt < 2; kt++) {
            int c = qc + kt * 16 + 2 * tig;
            aq[mt][kt][0] = *(const uint32_t*)&S[r0][c];
            aq[mt][kt][1] = *(const uint32_t*)&S[r0 + 8][c];
            if (kt == 0) {
                aq[mt][kt][2] = *(const uint32_t*)&S[r0][c + 8];
                aq[mt][kt][3] = *(const uint32_t*)&S[r0 + 8][c + 8];
            } else { aq[mt][kt][2] = 0u; aq[mt][kt][3] = 0u; }
        }
    }
    uint32_t bk[8][2][2];
    #pragma unroll
    for (int nt = 0; nt < 8; nt++) {
        int tok = nt * 8 + gid;
        #pragma unroll
        for (int kt = 0; kt < 2; kt++) {
            int c = kc + kt * 16 + 2 * tig;
            bk[nt][kt][0] = *(const uint32_t*)&S[tok][c];
            bk[nt][kt][1] = (kt == 0) ? *(const uint32_t*)&S[tok][c + 8] : 0u;
        }
    }
    __syncthreads();   // Vt complete before ldmatrix reads

    // ---- S = Q @ K^T ----
    float acc[2][8][4];
    #pragma unroll
    for (int mt = 0; mt < 2; mt++)
        #pragma unroll
        for (int nt = 0; nt < 8; nt++)
            #pragma unroll
            for (int q = 0; q < 4; q++) acc[mt][nt][q] = 0.0f;

    #pragma unroll
    for (int mt = 0; mt < 2; mt++)
        #pragma unroll
        for (int nt = 0; nt < 8; nt++)
            #pragma unroll
            for (int kt = 0; kt < 2; kt++)
                mma_bf16(acc[mt][nt], aq[mt][kt], bk[nt][kt]);

    // ---- masks ----
    const int wimg = win & 63;
    const int wi = wimg >> 3, wj = wimg & 7;
    int rk[8];
    #pragma unroll
    for (int nt = 0; nt < 8; nt++) {
        rk[nt] = ((wi == 7) ? ((nt < 4) ? 1 : 2) : 0) * 3
               + ((wj == 7) ? ((2 * tig < 4) ? 1 : 2) : 0);
    }

    const float K1 = 0.2944888985f;        // 24^-0.5 * log2(e)
    const float MASKL2 = -144.269504089f;  // -100 * log2(e)

    uint32_t p01[2][8], p23[2][8];
    #pragma unroll
    for (int mt = 0; mt < 2; mt++) {
        int n0 = mh * 32 + mt * 16 + gid;
        int n1 = n0 + 8;
        int rq0 = ((wi == 7) ? (((n0 >> 3) < 4) ? 1 : 2) : 0) * 3
                + ((wj == 7) ? (((n0 & 7) < 4) ? 1 : 2) : 0);
        int rq1 = ((wi == 7) ? (((n1 >> 3) < 4) ? 1 : 2) : 0) * 3
                + ((wj == 7) ? (((n1 & 7) < 4) ? 1 : 2) : 0);
        #pragma unroll
        for (int nt = 0; nt < 8; nt++) {
            const float4 bb = *(const float4*)&g_bias_exp[
                (((((head * 2 + mh) * 2 + mt) * 8 + nt) * 32 + lane) << 2)];
            float m0 = (rq0 != rk[nt]) ? MASKL2 : 0.0f;
            float m1 = (rq1 != rk[nt]) ? MASKL2 : 0.0f;
            float e00 = exp2_poly(acc[mt][nt][0] * K1 + bb.x + m0);
            float e01 = exp2_poly(acc[mt][nt][1] * K1 + bb.y + m0);
            float e10 = exp2_poly(acc[mt][nt][2] * K1 + bb.z + m1);
            float e11 = exp2_poly(acc[mt][nt][3] * K1 + bb.w + m1);
            __half2 h01 = __floats2half2_rn(e00, e01);
            __half2 h23 = __floats2half2_rn(e10, e11);
            p01[mt][nt] = *(uint32_t*)&h01;
            p23[mt][nt] = *(uint32_t*)&h23;
        }
    }

    // ---- load V^T B-fragments ----
    uint32_t bv[4][4][2];
    #pragma unroll
    for (int np = 0; np < 2; np++) {
        #pragma unroll
        for (int kt = 0; kt < 4; kt++) {
            int row = np * 16 + (lane & 7) + ((lane >> 4) << 3);
            int col = kt * 16 + (((lane >> 3) & 1) << 3);
            uint32_t addr = (uint32_t)__cvta_generic_to_shared(&Vt[head][row][col]);
            uint32_t r0, r1, r2, r3;
            ldm_x4(r0, r1, r2, r3, addr);
            bv[np*2  ][kt][0] = r0; bv[np*2  ][kt][1] = r1;
            bv[np*2+1][kt][0] = r2; bv[np*2+1][kt][1] = r3;
        }
    }

    // ---- O = P @ V ----
    float ao[2][4][4];
    #pragma unroll
    for (int mt = 0; mt < 2; mt++)
        #pragma unroll
        for (int nv = 0; nv < 4; nv++)
            #pragma unroll
            for (int q = 0; q < 4; q++) ao[mt][nv][q] = 0.0f;

    #pragma unroll
    for (int mt = 0; mt < 2; mt++) {
        #pragma unroll
        for (int kt = 0; kt < 4; kt++) {
            uint32_t ap[4] = { p01[mt][2*kt], p23[mt][2*kt],
                               p01[mt][2*kt+1], p23[mt][2*kt+1] };
            #pragma unroll
            for (int nv = 0; nv < 4; nv++)
                mma_f16(ao[mt][nv], ap, bv[nv][kt]);
        }
    }

    // ---- normalize & store ----
    #pragma unroll
    for (int mt = 0; mt < 2; mt++) {
        float sum0 = __shfl_sync(0xffffffffu, ao[mt][3][0], lane & 28);
        float sum1 = __shfl_sync(0xffffffffu, ao[mt][3][2], lane & 28);
        float inv0 = __fdividef(1.0f, sum0);
        float inv1 = __fdividef(1.0f, sum1);
        int row0 = win * 64 + mh * 32 + mt * 16 + gid;
        #pragma unroll
        for (int nv = 0; nv < 3; nv++) {
            int col = head * HD + nv * 8 + tig * 2;
            *(__nv_bfloat162*)&o[(size_t)row0 * CDIM + col] =
                __nv_bfloat162(__float2bfloat16(ao[mt][nv][0] * inv0),
                               __float2bfloat16(ao[mt][nv][1] * inv0));
            *(__nv_bfloat162*)&o[(size_t)(row0 + 8) * CDIM + col] =
                __nv_bfloat162(__float2bfloat16(ao[mt][nv][2] * inv1),
                               __float2bfloat16(ao[mt][nv][3] * inv1));
        }
    }
}

// ---------------- launch ----------------------------------------------------
extern "C" void kernel_launch(void* const* d_in, const int* in_sizes, int n_in,
                              void* d_out, int out_size)
{
    const float* x       = (const float*)d_in[0];
    const float* norm1_g = (const float*)d_in[1];
    const float* norm1_b = (const float*)d_in[2];
    const float* qkv_w   = (const float*)d_in[3];
    const float* qkv_b   = (const float*)d_in[4];
    const float* rpb     = (const float*)d_in[5];
    const float* proj_w  = (const float*)d_in[6];
    const float* proj_b  = (const float*)d_in[7];
    const float* norm2_g = (const float*)d_in[8];
    const float* norm2_b = (const float*)d_in[9];
    const float* fc1_w   = (const float*)d_in[10];
    const float* fc1_b   = (const float*)d_in[11];
    const float* fc2_w   = (const float*)d_in[12];
    const float* fc2_b   = (const float*)d_in[13];
    float* out = (float*)d_out;

    bf16 *hw_p, *qkv_p, *o_p, *h2_p, *fc1_p;
    bf16 *wqkv_p, *wproj_p, *wfc1_p, *wfc2_p;
    float *x1_p;
    cudaGetSymbolAddress((void**)&hw_p,   g_hw);
    cudaGetSymbolAddress((void**)&qkv_p,  g_qkv);
    cudaGetSymbolAddress((void**)&o_p,    g_o);
    cudaGetSymbolAddress((void**)&x1_p,   g_x1);
    cudaGetSymbolAddress((void**)&h2_p,   g_h2);
    cudaGetSymbolAddress((void**)&fc1_p,  g_fc1);
    cudaGetSymbolAddress((void**)&wqkv_p, g_wqkv);
    cudaGetSymbolAddress((void**)&wproj_p,g_wproj);
    cudaGetSymbolAddress((void**)&wfc1_p, g_wfc1);
    cudaGetSymbolAddress((void**)&wfc2_p, g_wfc2);

    cudaFuncSetAttribute(attn_tc, cudaFuncAttributeMaxDynamicSharedMemorySize,
                         ATTN_SMEM);

    conv_weights<<<(CH*CDIM + 255)/256, 256>>>(qkv_w, proj_w, fc1_w, fc2_w);
    build_bias<<<64, 256>>>(rpb);
    ln1_shift_window<<<TOKENS/4, 128>>>(x, norm1_g, norm1_b, hw_p);

    gemm_bf16<0><<<dim3(C3/96, TOKENS/128), 256>>>(hw_p, wqkv_p, qkv_b, nullptr,
                                                   qkv_p, CDIM, C3);

    attn_tc<<<NWIN, 256, ATTN_SMEM>>>(qkv_p, o_p);

    gemm_bf16<1><<<dim3(1, TOKENS/128), 256>>>(o_p, wproj_p, proj_b, x,
                                               x1_p, CDIM, CDIM);

    ln_plain<<<TOKENS/4, 128>>>(x1_p, norm2_g, norm2_b, h2_p);

    gemm_bf16<2><<<dim3(CH/96, TOKENS/128), 256>>>(h2_p, wfc1_p, fc1_b, nullptr,
                                                   fc1_p, CDIM, CH);

    gemm_bf16<3><<<dim3(1, TOKENS/128), 256>>>(fc1_p, wfc2_p, fc2_b, x1_p,
                                               out, CH, CDIM);
}

// round 7
// speedup vs baseline: 1.2686x; 1.0568x over previous
#include <cuda_runtime.h>
#include <cuda_bf16.h>
#include <cuda_fp16.h>
#include <cstdint>
#include <cstddef>

// ---------------- static problem sizes -------------------------------------
#define SS      4
#define NH      4
#define CDIM    96
#define HD      24
#define NWIN    4096
#define TOKENS  262144
#define C3      288
#define CH      384

typedef __nv_bfloat16 bf16;

// ---------------- scratch ---------------------------------------------------
__device__ bf16  g_hw [(size_t)TOKENS * CDIM];
__device__ bf16  g_qkv[(size_t)TOKENS * C3];
__device__ bf16  g_o  [(size_t)TOKENS * CDIM];
__device__ float g_x1 [(size_t)TOKENS * CDIM];
__device__ bf16  g_h2 [(size_t)TOKENS * CDIM];
__device__ bf16  g_fc1[(size_t)TOKENS * CH];
__device__ bf16  g_wqkv[C3 * CDIM];
__device__ bf16  g_wproj[CDIM * CDIM];
__device__ bf16  g_wfc1[CH * CDIM];
__device__ bf16  g_wfc2[CDIM * CH];
__device__ float g_bias_exp[16384];

// ---------------- asm helpers ----------------------------------------------
__device__ __forceinline__ void ldm_x4(uint32_t& r0, uint32_t& r1, uint32_t& r2,
                                       uint32_t& r3, uint32_t addr) {
    asm volatile("ldmatrix.sync.aligned.m8n8.x4.shared.b16 {%0,%1,%2,%3}, [%4];\n"
                 : "=r"(r0), "=r"(r1), "=r"(r2), "=r"(r3) : "r"(addr));
}
__device__ __forceinline__ void mma_bf16(float c[4], const uint32_t a[4],
                                         const uint32_t b[2]) {
    asm volatile(
        "mma.sync.aligned.m16n8k16.row.col.f32.bf16.bf16.f32 "
        "{%0,%1,%2,%3},{%4,%5,%6,%7},{%8,%9},{%0,%1,%2,%3};\n"
        : "+f"(c[0]), "+f"(c[1]), "+f"(c[2]), "+f"(c[3])
        : "r"(a[0]), "r"(a[1]), "r"(a[2]), "r"(a[3]), "r"(b[0]), "r"(b[1]));
}
__device__ __forceinline__ void mma_f16(float c[4], const uint32_t a[4],
                                        const uint32_t b[2]) {
    asm volatile(
        "mma.sync.aligned.m16n8k16.row.col.f32.f16.f16.f32 "
        "{%0,%1,%2,%3},{%4,%5,%6,%7},{%8,%9},{%0,%1,%2,%3};\n"
        : "+f"(c[0]), "+f"(c[1]), "+f"(c[2]), "+f"(c[3])
        : "r"(a[0]), "r"(a[1]), "r"(a[2]), "r"(a[3]), "r"(b[0]), "r"(b[1]));
}
__device__ __forceinline__ void cp16(uint32_t dst, const void* src) {
    asm volatile("cp.async.ca.shared.global [%0], [%1], 16;\n"
                 :: "r"(dst), "l"(src));
}
__device__ __forceinline__ void cp_commit() { asm volatile("cp.async.commit_group;\n"); }
__device__ __forceinline__ void cp_wait_all() { asm volatile("cp.async.wait_group 0;\n"); }

__device__ __forceinline__ float exp2_poly(float z) {
    z = fmaxf(z, -100.0f);
    float t = z + 12582912.0f;
    int   n = __float_as_int(t) - 0x4B400000;
    float f = z - (t - 12582912.0f);
    float p = 0.009618129107f;
    p = p * f + 0.05550410866f;
    p = p * f + 0.2402265069f;
    p = p * f + 0.69314718056f;
    p = p * f + 1.0f;
    return p * __int_as_float((n + 127) << 23);
}

// ---------------- weight conversion -----------------------------------------
__global__ void conv_weights(const float* __restrict__ a, const float* __restrict__ b,
                             const float* __restrict__ c, const float* __restrict__ d)
{
    int i = blockIdx.x * 256 + threadIdx.x;
    if (i < C3 * CDIM)   g_wqkv[i]  = __float2bfloat16(a[i]);
    if (i < CDIM * CDIM) g_wproj[i] = __float2bfloat16(b[i]);
    if (i < CH * CDIM) { g_wfc1[i]  = __float2bfloat16(c[i]);
                         g_wfc2[i]  = __float2bfloat16(d[i]); }
}

// ---------------- bias expansion (fragment-ordered, x log2e) ----------------
__global__ void build_bias(const float* __restrict__ rpb)
{
    int idx = blockIdx.x * 256 + threadIdx.x;
    int q    = idx & 3;
    int lane = (idx >> 2) & 31;
    int nt   = (idx >> 7) & 7;
    int mt   = (idx >> 10) & 1;
    int mh   = (idx >> 11) & 1;
    int head = (idx >> 12) & 3;
    int gid = lane >> 2, tig = lane & 3;
    int n = mh*32 + mt*16 + gid + ((q >> 1) << 3);
    int m = nt*8 + tig*2 + (q & 1);
    int ni = n >> 3, nj = n & 7, mi = m >> 3, mj = m & 7;
    int ridx = (ni - mi + 7) * 15 + (nj - mj + 7);
    g_bias_exp[idx] = rpb[ridx * NH + head] * 1.4426950408889634f;
}

// ---------------- vectorized LN helpers -------------------------------------
__device__ __forceinline__ void ln_row_v4(const float* __restrict__ xr,
                                          const float* __restrict__ g,
                                          const float* __restrict__ b,
                                          bf16* __restrict__ orow, int lane)
{
    float4 v = make_float4(0.f, 0.f, 0.f, 0.f);
    if (lane < 24) v = *(const float4*)(xr + lane * 4);
    float s  = v.x + v.y + v.z + v.w;
    float ss = v.x*v.x + v.y*v.y + v.z*v.z + v.w*v.w;
    #pragma unroll
    for (int o = 16; o; o >>= 1) {
        s  += __shfl_xor_sync(0xffffffffu, s,  o);
        ss += __shfl_xor_sync(0xffffffffu, ss, o);
    }
    float mu = s * (1.0f/CDIM);
    float rs = rsqrtf(ss * (1.0f/CDIM) - mu*mu + 1e-5f);
    if (lane < 24) {
        float4 gv = *(const float4*)(g + lane * 4);
        float4 bv = *(const float4*)(b + lane * 4);
        __nv_bfloat162 lo((__nv_bfloat16)((v.x - mu) * rs * gv.x + bv.x),
                          (__nv_bfloat16)((v.y - mu) * rs * gv.y + bv.y));
        __nv_bfloat162 hi((__nv_bfloat16)((v.z - mu) * rs * gv.z + bv.z),
                          (__nv_bfloat16)((v.w - mu) * rs * gv.w + bv.w));
        uint2 pk;
        pk.x = *(uint32_t*)&lo;
        pk.y = *(uint32_t*)&hi;
        *(uint2*)(orow + lane * 4) = pk;
    }
}

// ---------------- LN1 + shift + window partition (bf16 out) ----------------
__global__ void ln1_shift_window(const float* __restrict__ x,
                                 const float* __restrict__ g,
                                 const float* __restrict__ b,
                                 bf16* __restrict__ out)
{
    int tok  = blockIdx.x * 4 + (threadIdx.x >> 5);
    int lane = threadIdx.x & 31;
    int bimg = tok >> 12;
    int hw   = tok & 4095;
    int hi   = hw >> 6, wj = hw & 63;
    int i = (hi + 60) & 63;
    int j = (wj + 60) & 63;
    int dtok = ((bimg * 64 + (i >> 3) * 8 + (j >> 3)) << 6) + ((i & 7) << 3) + (j & 7);
    ln_row_v4(x + (size_t)tok * CDIM, g, b, out + (size_t)dtok * CDIM, lane);
}

// ---------------- plain LN (bf16 out) ---------------------------------------
__global__ void ln_plain(const float* __restrict__ x,
                         const float* __restrict__ g,
                         const float* __restrict__ b,
                         bf16* __restrict__ out)
{
    int tok  = blockIdx.x * 4 + (threadIdx.x >> 5);
    int lane = threadIdx.x & 31;
    ln_row_v4(x + (size_t)tok * CDIM, g, b, out + (size_t)tok * CDIM, lane);
}

// ---------------- bf16 tensor-core GEMM (3 blocks/SM) -----------------------
#define SROW 40

template<int MODE>
__global__ void __launch_bounds__(256, 3)
gemm_bf16(const bf16* __restrict__ A, const bf16* __restrict__ W,
          const float* __restrict__ bias, const float* __restrict__ aux,
          void* __restrict__ Cout, int K, int N)
{
    __shared__ bf16 As[2][128][SROW];
    __shared__ bf16 Bs[2][96][SROW];

    const int t    = threadIdx.x;
    const int bm   = blockIdx.y * 128;
    const int bn   = blockIdx.x * 96;
    const int warp = t >> 5, lane = t & 31;
    const int wrow = warp & 3;
    const int wcol = warp >> 2;
    const int gid  = lane >> 2, tig = lane & 3;

    float acc[2][6][4];
    #pragma unroll
    for (int i = 0; i < 2; i++)
        #pragma unroll
        for (int j = 0; j < 6; j++)
            #pragma unroll
            for (int q = 0; q < 4; q++) acc[i][j][q] = 0.0f;

    const int nk = K >> 5;

    auto issue = [&](int kt, int buf) {
        const int k0 = kt << 5;
        #pragma unroll
        for (int c = 0; c < 2; c++) {
            int cid = t + c * 256;
            int row = cid >> 2, cc = cid & 3;
            cp16((uint32_t)__cvta_generic_to_shared(&As[buf][row][cc * 8]),
                 A + (size_t)(bm + row) * K + k0 + cc * 8);
        }
        {
            int row = t >> 2, cc = t & 3;
            cp16((uint32_t)__cvta_generic_to_shared(&Bs[buf][row][cc * 8]),
                 W + (size_t)(bn + row) * K + k0 + cc * 8);
        }
        if (t < 128) {
            int cid = 256 + t;
            int row = cid >> 2, cc = cid & 3;
            cp16((uint32_t)__cvta_generic_to_shared(&Bs[buf][row][cc * 8]),
                 W + (size_t)(bn + row) * K + k0 + cc * 8);
        }
        cp_commit();
    };

    issue(0, 0);

    for (int kt = 0; kt < nk; kt++) {
        cp_wait_all();
        __syncthreads();
        if (kt + 1 < nk) issue(kt + 1, (kt + 1) & 1);
        const int buf = kt & 1;

        #pragma unroll
        for (int ks = 0; ks < 32; ks += 16) {
            uint32_t af[2][4];
            #pragma unroll
            for (int mt = 0; mt < 2; mt++) {
                int row = wrow * 32 + mt * 16 + (lane & 15);
                int col = ks + ((lane >> 4) << 3);
                uint32_t addr = (uint32_t)__cvta_generic_to_shared(&As[buf][row][col]);
                ldm_x4(af[mt][0], af[mt][1], af[mt][2], af[mt][3], addr);
            }
            uint32_t bfm[6][2];
            #pragma unroll
            for (int pr = 0; pr < 3; pr++) {
                int row = wcol * 48 + pr * 16 + (lane & 7) + ((lane >> 4) << 3);
                int col = ks + (((lane >> 3) & 1) << 3);
                uint32_t addr = (uint32_t)__cvta_generic_to_shared(&Bs[buf][row][col]);
                uint32_t r0, r1, r2, r3;
                ldm_x4(r0, r1, r2, r3, addr);
                bfm[pr*2  ][0] = r0; bfm[pr*2  ][1] = r1;
                bfm[pr*2+1][0] = r2; bfm[pr*2+1][1] = r3;
            }
            #pragma unroll
            for (int mt = 0; mt < 2; mt++)
                #pragma unroll
                for (int nt = 0; nt < 6; nt++)
                    mma_bf16(acc[mt][nt], af[mt], bfm[nt]);
        }
        __syncthreads();
    }

    #pragma unroll
    for (int mt = 0; mt < 2; mt++) {
        const int r0 = bm + wrow * 32 + mt * 16 + gid;
        const int r1 = r0 + 8;
        int d0 = r0, d1 = r1;
        if (MODE == 1) {
            int w0 = (r0 >> 6) & 63, s0 = r0 & 63;
            int i0 = ((w0 >> 3) << 3) + (s0 >> 3), j0 = ((w0 & 7) << 3) + (s0 & 7);
            d0 = (r0 & ~4095) | ((((i0 + SS) & 63) << 6) | ((j0 + SS) & 63));
            int w1 = (r1 >> 6) & 63, s1 = r1 & 63;
            int i1 = ((w1 >> 3) << 3) + (s1 >> 3), j1 = ((w1 & 7) << 3) + (s1 & 7);
            d1 = (r1 & ~4095) | ((((i1 + SS) & 63) << 6) | ((j1 + SS) & 63));
        }
        #pragma unroll
        for (int nt = 0; nt < 6; nt++) {
            const int col = bn + wcol * 48 + nt * 8 + tig * 2;
            const float b0 = bias[col], b1 = bias[col + 1];
            float v00 = acc[mt][nt][0] + b0;
            float v01 = acc[mt][nt][1] + b1;
            float v10 = acc[mt][nt][2] + b0;
            float v11 = acc[mt][nt][3] + b1;
            if (MODE == 0) {
                bf16* C = (bf16*)Cout;
                *(__nv_bfloat162*)&C[(size_t)r0 * N + col] =
                    __nv_bfloat162(__float2bfloat16(v00), __float2bfloat16(v01));
                *(__nv_bfloat162*)&C[(size_t)r1 * N + col] =
                    __nv_bfloat162(__float2bfloat16(v10), __float2bfloat16(v11));
            } else if (MODE == 1) {
                float* C = (float*)Cout;
                size_t o0 = (size_t)d0 * CDIM + col;
                size_t o1 = (size_t)d1 * CDIM + col;
                float2 x0 = *(const float2*)&aux[o0];
                float2 x1v = *(const float2*)&aux[o1];
                *(float2*)&C[o0] = make_float2(v00 + x0.x,  v01 + x0.y);
                *(float2*)&C[o1] = make_float2(v10 + x1v.x, v11 + x1v.y);
            } else if (MODE == 2) {
                v00 = 0.5f * v00 * (1.0f + erff(v00 * 0.70710678118654752f));
                v01 = 0.5f * v01 * (1.0f + erff(v01 * 0.70710678118654752f));
                v10 = 0.5f * v10 * (1.0f + erff(v10 * 0.70710678118654752f));
                v11 = 0.5f * v11 * (1.0f + erff(v11 * 0.70710678118654752f));
                bf16* C = (bf16*)Cout;
                *(__nv_bfloat162*)&C[(size_t)r0 * N + col] =
                    __nv_bfloat162(__float2bfloat16(v00), __float2bfloat16(v01));
                *(__nv_bfloat162*)&C[(size_t)r1 * N + col] =
                    __nv_bfloat162(__float2bfloat16(v10), __float2bfloat16(v11));
            } else {
                float* C = (float*)Cout;
                float2 x0 = *(const float2*)&aux[(size_t)r0 * N + col];
                float2 x1v = *(const float2*)&aux[(size_t)r1 * N + col];
                *(float2*)&C[(size_t)r0 * N + col] = make_float2(v00 + x0.x,  v01 + x0.y);
                *(float2*)&C[(size_t)r1 * N + col] = make_float2(v10 + x1v.x, v11 + x1v.y);
            }
        }
    }
}

// ---------------- tensor-core windowed attention (smem-staged) --------------
#define ATTN_SMEM (37888 + 18432)

__global__ void __launch_bounds__(256)
attn_tc(const bf16* __restrict__ qkv, bf16* __restrict__ o)
{
    extern __shared__ __align__(16) char sm_[];
    bf16  (*S)[296]      = (bf16(*)[296])sm_;
    __half (*Vt)[32][72] = (__half(*)[32][72])(sm_ + 37888);

    const int win  = blockIdx.x;
    const int t    = threadIdx.x;
    const int warp = t >> 5, lane = t & 31;
    const int head = warp >> 1, mh = warp & 1;
    const int gid  = lane >> 2, tig = lane & 3;

    const bf16* wq = qkv + (size_t)win * 64 * C3;

    #pragma unroll
    for (int i = 0; i < 9; i++) {
        int cid = t + i * 256;
        int row = cid / 36, c = cid % 36;
        cp16((uint32_t)__cvta_generic_to_shared(&S[row][c * 8]),
             wq + (size_t)row * C3 + c * 8);
    }
    cp_commit();
    cp_wait_all();
    __syncthreads();

    {
        int tok = t & 63, h = t >> 6;
        const bf16* vsrc = &S[tok][192 + h * HD];
        #pragma unroll
        for (int d = 0; d < HD; d++)
            Vt[h][d][tok] = __float2half(__bfloat162float(vsrc[d]));
        Vt[h][24][tok] = __float2half(1.0f);
        #pragma unroll
        for (int d = 25; d < 32; d++)
            Vt[h][d][tok] = __float2half(0.0f);
    }

    const int qc = head * HD;
    const int kc = 96 + head * HD;

    uint32_t aq[2][2][4];
    #pragma unroll
    for (int mt = 0; mt < 2; mt++) {
        int r0 = mh * 32 + mt * 16 + gid;
        #pragma unroll
        for (int kt = 0; kt < 2; kt++) {
            int c = qc + kt * 16 + 2 * tig;
            aq[mt][kt][0] = *(const uint32_t*)&S[r0][c];
            aq[mt][kt][1] = *(const uint32_t*)&S[r0 + 8][c];
            if (kt == 0) {
                aq[mt][kt][2] = *(const uint32_t*)&S[r0][c + 8];
                aq[mt][kt][3] = *(const uint32_t*)&S[r0 + 8][c + 8];
            } else { aq[mt][kt][2] = 0u; aq[mt][kt][3] = 0u; }
        }
    }
    uint32_t bk[8][2][2];
    #pragma unroll
    for (int nt = 0; nt < 8; nt++) {
        int tok = nt * 8 + gid;
        #pragma unroll
        for (int kt = 0; kt < 2; kt++) {
            int c = kc + kt * 16 + 2 * tig;
            bk[nt][kt][0] = *(const uint32_t*)&S[tok][c];
            bk[nt][kt][1] = (kt == 0) ? *(const uint32_t*)&S[tok][c + 8] : 0u;
        }
    }
    __syncthreads();

    float acc[2][8][4];
    #pragma unroll
    for (int mt = 0; mt < 2; mt++)
        #pragma unroll
        for (int nt = 0; nt < 8; nt++)
            #pragma unroll
            for (int q = 0; q < 4; q++) acc[mt][nt][q] = 0.0f;

    #pragma unroll
    for (int mt = 0; mt < 2; mt++)
        #pragma unroll
        for (int nt = 0; nt < 8; nt++)
            #pragma unroll
            for (int kt = 0; kt < 2; kt++)
                mma_bf16(acc[mt][nt], aq[mt][kt], bk[nt][kt]);

    const int wimg = win & 63;
    const int wi = wimg >> 3, wj = wimg & 7;
    int rk[8];
    #pragma unroll
    for (int nt = 0; nt < 8; nt++) {
        rk[nt] = ((wi == 7) ? ((nt < 4) ? 1 : 2) : 0) * 3
               + ((wj == 7) ? ((2 * tig < 4) ? 1 : 2) : 0);
    }

    const float K1 = 0.2944888985f;
    const float MASKL2 = -144.269504089f;

    uint32_t p01[2][8], p23[2][8];
    #pragma unroll
    for (int mt = 0; mt < 2; mt++) {
        int n0 = mh * 32 + mt * 16 + gid;
        int n1 = n0 + 8;
        int rq0 = ((wi == 7) ? (((n0 >> 3) < 4) ? 1 : 2) : 0) * 3
                + ((wj == 7) ? (((n0 & 7) < 4) ? 1 : 2) : 0);
        int rq1 = ((wi == 7) ? (((n1 >> 3) < 4) ? 1 : 2) : 0) * 3
                + ((wj == 7) ? (((n1 & 7) < 4) ? 1 : 2) : 0);
        #pragma unroll
        for (int nt = 0; nt < 8; nt++) {
            const float4 bb = *(const float4*)&g_bias_exp[
                (((((head * 2 + mh) * 2 + mt) * 8 + nt) * 32 + lane) << 2)];
            float m0 = (rq0 != rk[nt]) ? MASKL2 : 0.0f;
            float m1 = (rq1 != rk[nt]) ? MASKL2 : 0.0f;
            float e00 = exp2_poly(acc[mt][nt][0] * K1 + bb.x + m0);
            float e01 = exp2_poly(acc[mt][nt][1] * K1 + bb.y + m0);
            float e10 = exp2_poly(acc[mt][nt][2] * K1 + bb.z + m1);
            float e11 = exp2_poly(acc[mt][nt][3] * K1 + bb.w + m1);
            __half2 h01 = __floats2half2_rn(e00, e01);
            __half2 h23 = __floats2half2_rn(e10, e11);
            p01[mt][nt] = *(uint32_t*)&h01;
            p23[mt][nt] = *(uint32_t*)&h23;
        }
    }

    uint32_t bv[4][4][2];
    #pragma unroll
    for (int np = 0; np < 2; np++) {
        #pragma unroll
        for (int kt = 0; kt < 4; kt++) {
            int row = np * 16 + (lane & 7) + ((lane >> 4) << 3);
            int col = kt * 16 + (((lane >> 3) & 1) << 3);
            uint32_t addr = (uint32_t)__cvta_generic_to_shared(&Vt[head][row][col]);
            uint32_t r0, r1, r2, r3;
            ldm_x4(r0, r1, r2, r3, addr);
            bv[np*2  ][kt][0] = r0; bv[np*2  ][kt][1] = r1;
            bv[np*2+1][kt][0] = r2; bv[np*2+1][kt][1] = r3;
        }
    }

    float ao[2][4][4];
    #pragma unroll
    for (int mt = 0; mt < 2; mt++)
        #pragma unroll
        for (int nv = 0; nv < 4; nv++)
            #pragma unroll
            for (int q = 0; q < 4; q++) ao[mt][nv][q] = 0.0f;

    #pragma unroll
    for (int mt = 0; mt < 2; mt++) {
        #pragma unroll
        for (int kt = 0; kt < 4; kt++) {
            uint32_t ap[4] = { p01[mt][2*kt], p23[mt][2*kt],
                               p01[mt][2*kt+1], p23[mt][2*kt+1] };
            #pragma unroll
            for (int nv = 0; nv < 4; nv++)
                mma_f16(ao[mt][nv], ap, bv[nv][kt]);
        }
    }

    #pragma unroll
    for (int mt = 0; mt < 2; mt++) {
        float sum0 = __shfl_sync(0xffffffffu, ao[mt][3][0], lane & 28);
        float sum1 = __shfl_sync(0xffffffffu, ao[mt][3][2], lane & 28);
        float inv0 = __fdividef(1.0f, sum0);
        float inv1 = __fdividef(1.0f, sum1);
        int row0 = win * 64 + mh * 32 + mt * 16 + gid;
        #pragma unroll
        for (int nv = 0; nv < 3; nv++) {
            int col = head * HD + nv * 8 + tig * 2;
            *(__nv_bfloat162*)&o[(size_t)row0 * CDIM + col] =
                __nv_bfloat162(__float2bfloat16(ao[mt][nv][0] * inv0),
                               __float2bfloat16(ao[mt][nv][1] * inv0));
            *(__nv_bfloat162*)&o[(size_t)(row0 + 8) * CDIM + col] =
                __nv_bfloat162(__float2bfloat16(ao[mt][nv][2] * inv1),
                               __float2bfloat16(ao[mt][nv][3] * inv1));
        }
    }
}

// ---------------- launch ----------------------------------------------------
extern "C" void kernel_launch(void* const* d_in, const int* in_sizes, int n_in,
                              void* d_out, int out_size)
{
    const float* x       = (const float*)d_in[0];
    const float* norm1_g = (const float*)d_in[1];
    const float* norm1_b = (const float*)d_in[2];
    const float* qkv_w   = (const float*)d_in[3];
    const float* qkv_b   = (const float*)d_in[4];
    const float* rpb     = (const float*)d_in[5];
    const float* proj_w  = (const float*)d_in[6];
    const float* proj_b  = (const float*)d_in[7];
    const float* norm2_g = (const float*)d_in[8];
    const float* norm2_b = (const float*)d_in[9];
    const float* fc1_w   = (const float*)d_in[10];
    const float* fc1_b   = (const float*)d_in[11];
    const float* fc2_w   = (const float*)d_in[12];
    const float* fc2_b   = (const float*)d_in[13];
    float* out = (float*)d_out;

    bf16 *hw_p, *qkv_p, *o_p, *h2_p, *fc1_p;
    bf16 *wqkv_p, *wproj_p, *wfc1_p, *wfc2_p;
    float *x1_p;
    cudaGetSymbolAddress((void**)&hw_p,   g_hw);
    cudaGetSymbolAddress((void**)&qkv_p,  g_qkv);
    cudaGetSymbolAddress((void**)&o_p,    g_o);
    cudaGetSymbolAddress((void**)&x1_p,   g_x1);
    cudaGetSymbolAddress((void**)&h2_p,   g_h2);
    cudaGetSymbolAddress((void**)&fc1_p,  g_fc1);
    cudaGetSymbolAddress((void**)&wqkv_p, g_wqkv);
    cudaGetSymbolAddress((void**)&wproj_p,g_wproj);
    cudaGetSymbolAddress((void**)&wfc1_p, g_wfc1);
    cudaGetSymbolAddress((void**)&wfc2_p, g_wfc2);

    cudaFuncSetAttribute(attn_tc, cudaFuncAttributeMaxDynamicSharedMemorySize,
                         ATTN_SMEM);

    conv_weights<<<(CH*CDIM + 255)/256, 256>>>(qkv_w, proj_w, fc1_w, fc2_w);
    build_bias<<<64, 256>>>(rpb);
    ln1_shift_window<<<TOKENS/4, 128>>>(x, norm1_g, norm1_b, hw_p);

    gemm_bf16<0><<<dim3(C3/96, TOKENS/128), 256>>>(hw_p, wqkv_p, qkv_b, nullptr,
                                                   qkv_p, CDIM, C3);

    attn_tc<<<NWIN, 256, ATTN_SMEM>>>(qkv_p, o_p);

    gemm_bf16<1><<<dim3(1, TOKENS/128), 256>>>(o_p, wproj_p, proj_b, x,
                                               x1_p, CDIM, CDIM);

    ln_plain<<<TOKENS/4, 128>>>(x1_p, norm2_g, norm2_b, h2_p);

    gemm_bf16<2><<<dim3(CH/96, TOKENS/128), 256>>>(h2_p, wfc1_p, fc1_b, nullptr,
                                                   fc1_p, CDIM, CH);

    gemm_bf16<3><<<dim3(1, TOKENS/128), 256>>>(fc1_p, wfc2_p, fc2_b, x1_p,
                                               out, CH, CDIM);
}